// round 11
// baseline (speedup 1.0000x reference)
#include <cuda_runtime.h>
#include <cuda_fp16.h>
#include <cstdint>

// Problem constants
#define B_     4096
#define D_INN  4096
#define D_PROJ 1024
#define N_CLS  32
#define NC0    32
#define NC1    64

// Output layout: (parent_logits, child0, child1, parent_proj, child_proj) flattened fp32
#define OFF_PLOG 0
#define OFF_C0   (B_ * N_CLS)                 // 131072
#define OFF_C1   (OFF_C0 + B_ * NC0)          // 262144
#define OFF_P    (OFF_C1 + B_ * NC1)          // 524288
#define OFF_S    (OFF_P + B_ * D_PROJ)        // 4718592

#define WSCALE 4096.0f
#define OSCALE (1.0f / 4096.0f)

// fp16 scratch + bucket state (static device globals: allocation-free)
__device__ __align__(16) __half g_xh[B_ * D_INN];            // 32 MB
__device__ __align__(16) __half g_wph[D_INN * D_PROJ];       // 8 MB (x WSCALE)
__device__ __align__(16) __half g_wsh[D_INN * D_PROJ];       // 8 MB (x WSCALE)
__device__ __align__(16) __half g_ph[B_ * D_PROJ];           // 8 MB, P fp16
__device__ __align__(16) __half g_sh[B_ * D_PROJ];           // 8 MB, S fp16
__device__ __align__(16) __half g_cwh[N_CLS * 96 * D_PROJ];  // 6 MB, merged cw (x WSCALE)
__device__ __align__(16) __half g_wch[D_PROJ * N_CLS];       // 64 KB, Wc (x WSCALE)
__device__ int g_cnt[N_CLS];
__device__ int g_idx[N_CLS][B_];

// ===========================================================================
// helpers
// ===========================================================================
__device__ __forceinline__ uint32_t smem_u32(const void* p) {
    uint32_t a;
    asm("{ .reg .u64 t; cvta.to.shared.u64 t, %1; cvt.u32.u64 %0, t; }" : "=r"(a) : "l"(p));
    return a;
}

__device__ __forceinline__ uint32_t f2h2(float hi, float lo) {
    uint32_t r;
    asm("cvt.rn.f16x2.f32 %0, %1, %2;" : "=r"(r) : "f"(hi), "f"(lo));
    return r;
}

__device__ __forceinline__ void ldsm_x4(uint32_t* r, uint32_t addr) {
    asm volatile("ldmatrix.sync.aligned.m8n8.x4.shared.b16 {%0,%1,%2,%3}, [%4];"
                 : "=r"(r[0]), "=r"(r[1]), "=r"(r[2]), "=r"(r[3]) : "r"(addr));
}
__device__ __forceinline__ void ldsm_x4_t(uint32_t* r, uint32_t addr) {
    asm volatile("ldmatrix.sync.aligned.m8n8.x4.trans.shared.b16 {%0,%1,%2,%3}, [%4];"
                 : "=r"(r[0]), "=r"(r[1]), "=r"(r[2]), "=r"(r[3]) : "r"(addr));
}

__device__ __forceinline__ void mma_f16(float* d, const uint32_t* a, const uint32_t* b) {
    asm volatile(
        "mma.sync.aligned.m16n8k16.row.col.f32.f16.f16.f32 "
        "{%0,%1,%2,%3}, {%4,%5,%6,%7}, {%8,%9}, {%0,%1,%2,%3};"
        : "+f"(d[0]), "+f"(d[1]), "+f"(d[2]), "+f"(d[3])
        : "r"(a[0]), "r"(a[1]), "r"(a[2]), "r"(a[3]), "r"(b[0]), "r"(b[1]));
}

#define CP_ASYNC16(saddr, gaddr) \
    asm volatile("cp.async.cg.shared.global [%0], [%1], 16;" :: "r"(saddr), "l"(gaddr))
#define CP_COMMIT() asm volatile("cp.async.commit_group;" ::: "memory")
#define CP_WAIT1()  asm volatile("cp.async.wait_group 1;"  ::: "memory")

// ===========================================================================
// K0: fp32 -> fp16 pre-conversion (unchanged from R10).
// ===========================================================================
#define NXF4  (B_ * D_INN / 4)           // 4194304
#define NWF4  (D_INN * D_PROJ / 4)       // 1048576
#define NCWF4 (N_CLS * 96 * D_PROJ / 4)  // 786432
#define NWCF4 (D_PROJ * N_CLS / 4)       // 8192
#define NCONV (NXF4 + 2 * NWF4 + NCWF4 + NWCF4)
#define NCONV2 (NCONV / 2)

__global__ __launch_bounds__(256)
void convert_kernel(const float* __restrict__ x,
                    const float* __restrict__ Wp, const float* __restrict__ Ws,
                    const float* __restrict__ cw0, const float* __restrict__ cw1,
                    const float* __restrict__ Wc)
{
    if (blockIdx.x == 0 && threadIdx.x < N_CLS) g_cnt[threadIdx.x] = 0;

    const int p = blockIdx.x * blockDim.x + threadIdx.x;
    if (p >= NCONV2) return;
    const int i = p * 2;

    if (i < NXF4) {
        float4 v0 = *reinterpret_cast<const float4*>(x + (size_t)i * 4);
        float4 v1 = *reinterpret_cast<const float4*>(x + (size_t)i * 4 + 4);
        uint4 h = { f2h2(v0.y, v0.x), f2h2(v0.w, v0.z), f2h2(v1.y, v1.x), f2h2(v1.w, v1.z) };
        *reinterpret_cast<uint4*>(&g_xh[(size_t)i * 4]) = h;
    } else if (i < NXF4 + NWF4) {
        const int j = i - NXF4;
        float4 v0 = *reinterpret_cast<const float4*>(Wp + (size_t)j * 4);
        float4 v1 = *reinterpret_cast<const float4*>(Wp + (size_t)j * 4 + 4);
        uint4 h = { f2h2(v0.y * WSCALE, v0.x * WSCALE), f2h2(v0.w * WSCALE, v0.z * WSCALE),
                    f2h2(v1.y * WSCALE, v1.x * WSCALE), f2h2(v1.w * WSCALE, v1.z * WSCALE) };
        *reinterpret_cast<uint4*>(&g_wph[(size_t)j * 4]) = h;
    } else if (i < NXF4 + 2 * NWF4) {
        const int j = i - NXF4 - NWF4;
        float4 v0 = *reinterpret_cast<const float4*>(Ws + (size_t)j * 4);
        float4 v1 = *reinterpret_cast<const float4*>(Ws + (size_t)j * 4 + 4);
        uint4 h = { f2h2(v0.y * WSCALE, v0.x * WSCALE), f2h2(v0.w * WSCALE, v0.z * WSCALE),
                    f2h2(v1.y * WSCALE, v1.x * WSCALE), f2h2(v1.w * WSCALE, v1.z * WSCALE) };
        *reinterpret_cast<uint4*>(&g_wsh[(size_t)j * 4]) = h;
    } else if (i < NXF4 + 2 * NWF4 + NCWF4) {
        const int j = i - NXF4 - 2 * NWF4;
        float4 v[2];
        #pragma unroll
        for (int q = 0; q < 2; q++) {
            const int f = (j + q) * 4;
            const int k = f & (D_PROJ - 1);
            const int o = (f >> 10) % 96;
            const int c = f / (96 * D_PROJ);
            const float* src = (o < NC0)
                ? (cw0 + ((size_t)(c * NC0 + o) * D_PROJ + k))
                : (cw1 + ((size_t)(c * NC1 + (o - NC0)) * D_PROJ + k));
            v[q] = *reinterpret_cast<const float4*>(src);
        }
        uint4 h = { f2h2(v[0].y * WSCALE, v[0].x * WSCALE), f2h2(v[0].w * WSCALE, v[0].z * WSCALE),
                    f2h2(v[1].y * WSCALE, v[1].x * WSCALE), f2h2(v[1].w * WSCALE, v[1].z * WSCALE) };
        *reinterpret_cast<uint4*>(&g_cwh[(size_t)j * 4]) = h;
    } else {
        const int j = i - NXF4 - 2 * NWF4 - NCWF4;
        float4 v0 = *reinterpret_cast<const float4*>(Wc + (size_t)j * 4);
        float4 v1 = *reinterpret_cast<const float4*>(Wc + (size_t)j * 4 + 4);
        uint4 h = { f2h2(v0.y * WSCALE, v0.x * WSCALE), f2h2(v0.w * WSCALE, v0.z * WSCALE),
                    f2h2(v1.y * WSCALE, v1.x * WSCALE), f2h2(v1.w * WSCALE, v1.z * WSCALE) };
        *reinterpret_cast<uint4*>(&g_wch[(size_t)j * 4]) = h;
    }
}

// ===========================================================================
// K1: fused dual-output fp16 TC GEMM: one CTA computes the (m,n) tile of BOTH
// P = x@Wp and S = x@Ws (A staged once, two B stages). 256 threads = 8 warps
// (4m x 2n), warp tile 32x64 per output. 3-stage cp.async, BK=64, ring-unrolled
// constant smem bases. Bucket pass runs as the by==32 row.
// ===========================================================================
#define STAGES 3
#define BKH    64
#define A_ST_BYTES  (128 * 128)   // 16384
#define BB_ST_BYTES (64 * 256)    // 16384 per B matrix
#define ST_BYTES    (A_ST_BYTES + 2 * BB_ST_BYTES)  // 49152
#define SMEM_GEMM   (STAGES * ST_BYTES)             // 147456

__global__ __launch_bounds__(256, 1)
void hgemm_fused(const int* __restrict__ y,
                 const float* __restrict__ bp, const float* __restrict__ bs,
                 float* __restrict__ out)
{
    if (blockIdx.y == 32) {
        // bucket row: 8 blocks x 256 threads x 2 samples = 4096
        const int b0 = blockIdx.x * 512 + threadIdx.x;
        #pragma unroll
        for (int q = 0; q < 2; q++) {
            const int b = b0 + q * 256;
            const int c = y[b];
            const int p = atomicAdd(&g_cnt[c], 1);
            g_idx[c][p] = b;
        }
        return;
    }

    extern __shared__ char sm[];
    const uint32_t sb = smem_u32(sm);

    const int tid  = threadIdx.x;
    const int warp = tid >> 5;
    const int lane = tid & 31;
    const int wm   = warp >> 1;   // 0..3 (32 rows each)
    const int wn   = warp & 1;    // 0..1 (64 cols each)
    const int mblk = blockIdx.y * 128;
    const int nblk = blockIdx.x * 128;

    const int lm_row = (lane & 7) + ((lane >> 3) & 1) * 8;  // 0..15
    const int hi     = lane >> 4;                           // 0..1
    const int rm     = lm_row & 7;

    // acc[out][mt][nt][4]
    float acc[2][2][8][4];
    #pragma unroll
    for (int o = 0; o < 2; o++)
        #pragma unroll
        for (int mt = 0; mt < 2; mt++)
            #pragma unroll
            for (int nt = 0; nt < 8; nt++)
                #pragma unroll
                for (int i = 0; i < 4; i++) acc[o][mt][nt][i] = 0.f;

    auto issue = [&](uint32_t abase, int t) {
        const uint32_t bpb = abase + A_ST_BYTES;
        const uint32_t bsb = bpb + BB_ST_BYTES;
        #pragma unroll
        for (int j = 0; j < 4; j++) {              // A: 1024 chunks
            const int id  = tid + 256 * j;
            const int row = id >> 3, c = id & 7;
            const __half* g = g_xh + (size_t)(mblk + row) * D_INN + t * BKH + c * 8;
            CP_ASYNC16(abase + row * 128 + ((c ^ (row & 7)) << 4), g);
        }
        #pragma unroll
        for (int j = 0; j < 4; j++) {              // Bp: 1024 chunks
            const int id = tid + 256 * j;
            const int k  = id >> 4, c = id & 15;
            const __half* g = g_wph + (size_t)(t * BKH + k) * D_PROJ + nblk + c * 8;
            CP_ASYNC16(bpb + k * 256 + ((c ^ (k & 7)) << 4), g);
        }
        #pragma unroll
        for (int j = 0; j < 4; j++) {              // Bs: 1024 chunks
            const int id = tid + 256 * j;
            const int k  = id >> 4, c = id & 15;
            const __half* g = g_wsh + (size_t)(t * BKH + k) * D_PROJ + nblk + c * 8;
            CP_ASYNC16(bsb + k * 256 + ((c ^ (k & 7)) << 4), g);
        }
    };

    auto body = [&](int t, uint32_t cbase, uint32_t pbase) {
        CP_WAIT1();
        __syncthreads();

        if (t + 2 < 64)
            issue(pbase, t + 2);
        CP_COMMIT();

        const uint32_t bpb = cbase + A_ST_BYTES;
        const uint32_t bsb = bpb + BB_ST_BYTES;

        #pragma unroll
        for (int s = 0; s < 4; s++) {
            uint32_t afr[2][4], bfp[8][2], bfs[8][2];
            #pragma unroll
            for (int mt = 0; mt < 2; mt++) {
                const int row0 = wm * 32 + mt * 16 + lm_row;
                ldsm_x4(afr[mt], cbase + (uint32_t)(row0 * 128)
                                       + ((uint32_t)((2 * s + hi) ^ rm) << 4));
            }
            const int krow = 16 * s + lm_row;
            #pragma unroll
            for (int nb = 0; nb < 4; nb++) {
                const uint32_t coff = (uint32_t)((wn * 8 + nb * 2 + hi) ^ rm) << 4;
                uint32_t r[4];
                ldsm_x4_t(r, bpb + (uint32_t)(krow * 256) + coff);
                bfp[2 * nb][0] = r[0]; bfp[2 * nb][1] = r[1];
                bfp[2 * nb + 1][0] = r[2]; bfp[2 * nb + 1][1] = r[3];
                ldsm_x4_t(r, bsb + (uint32_t)(krow * 256) + coff);
                bfs[2 * nb][0] = r[0]; bfs[2 * nb][1] = r[1];
                bfs[2 * nb + 1][0] = r[2]; bfs[2 * nb + 1][1] = r[3];
            }
            #pragma unroll
            for (int mt = 0; mt < 2; mt++)
                #pragma unroll
                for (int nt = 0; nt < 8; nt++) {
                    mma_f16(acc[0][mt][nt], afr[mt], bfp[nt]);
                    mma_f16(acc[1][mt][nt], afr[mt], bfs[nt]);
                }
        }
    };

    const uint32_t s0 = sb, s1 = sb + ST_BYTES, s2 = sb + 2 * ST_BYTES;

    issue(s0, 0); CP_COMMIT();
    issue(s1, 1); CP_COMMIT();

    for (int t = 0; t < 63; t += 3) {
        body(t,     s0, s2);
        body(t + 1, s1, s0);
        body(t + 2, s2, s1);
    }
    body(63, s0, s2);

    // ---- epilogue: unscale, add bias, store fp32 + fp16 copies ----
    const int gid = lane >> 2;
    const int tig = lane & 3;
    #pragma unroll
    for (int o = 0; o < 2; o++) {
        float* C = out + (o ? OFF_S : OFF_P);
        __half* Ch = o ? g_sh : g_ph;
        const float* bias = o ? bs : bp;
        #pragma unroll
        for (int mt = 0; mt < 2; mt++) {
            const int row = mblk + wm * 32 + mt * 16 + gid;
            #pragma unroll
            for (int nt = 0; nt < 8; nt++) {
                const int col = nblk + wn * 64 + nt * 8 + 2 * tig;
                const float b0 = bias[col], b1 = bias[col + 1];
                float2 v0 = { acc[o][mt][nt][0] * OSCALE + b0, acc[o][mt][nt][1] * OSCALE + b1 };
                float2 v1 = { acc[o][mt][nt][2] * OSCALE + b0, acc[o][mt][nt][3] * OSCALE + b1 };
                *reinterpret_cast<float2*>(&C[(size_t)row * D_PROJ + col])       = v0;
                *reinterpret_cast<float2*>(&C[(size_t)(row + 8) * D_PROJ + col]) = v1;
                *reinterpret_cast<uint32_t*>(&Ch[(size_t)row * D_PROJ + col])       = f2h2(v0.y, v0.x);
                *reinterpret_cast<uint32_t*>(&Ch[(size_t)(row + 8) * D_PROJ + col]) = f2h2(v1.y, v1.x);
            }
        }
    }
}

// ===========================================================================
// K2: tensor-core tail (unchanged from R10).
// Blocks [0,32):  plog  = Ph @ Wch * OSCALE + bc
// Blocks [32,160): child = gathered Sh rows @ cwh[c]^T * OSCALE + cb
// ===========================================================================
#define STP (16384 + 64 * 80)    // 21504
#define STC (16384 + 96 * 128)   // 28672
#define SMEM_TAIL (3 * STC)      // 86016

__global__ __launch_bounds__(128)
void tail_kernel(const float* __restrict__ bc,
                 const float* __restrict__ cb0, const float* __restrict__ cb1,
                 float* __restrict__ out)
{
    extern __shared__ char sm[];
    const uint32_t sb = smem_u32(sm);

    const int tid  = threadIdx.x;
    const int warp = tid >> 5;
    const int lane = tid & 31;
    const int lm_row = (lane & 7) + ((lane >> 3) & 1) * 8;
    const int hi     = lane >> 4;
    const int rm     = lm_row & 7;
    const int gid    = lane >> 2;
    const int tig    = lane & 3;
    const int wm     = warp;

    if (blockIdx.x < 32) {
        const int mblk = blockIdx.x * 128;

        float acc[2][4][4];
        #pragma unroll
        for (int mt = 0; mt < 2; mt++)
            #pragma unroll
            for (int nt = 0; nt < 4; nt++)
                #pragma unroll
                for (int i = 0; i < 4; i++) acc[mt][nt][i] = 0.f;

        auto issue = [&](int slot, int t) {
            const uint32_t abase = sb + slot * STP;
            const uint32_t bbase = abase + 16384;
            #pragma unroll
            for (int j = 0; j < 8; j++) {
                const int id = tid + 128 * j;
                const int row = id >> 3, c = id & 7;
                const __half* g = g_ph + (size_t)(mblk + row) * D_PROJ + t * 64 + c * 8;
                CP_ASYNC16(abase + row * 128 + ((c ^ (row & 7)) << 4), g);
            }
            #pragma unroll
            for (int j = 0; j < 2; j++) {
                const int id = tid + 128 * j;
                const int row = id >> 2, c = id & 3;
                const __half* g = g_wch + (size_t)(t * 64 + row) * N_CLS + c * 8;
                CP_ASYNC16(bbase + row * 80 + c * 16, g);
            }
        };

        issue(0, 0); CP_COMMIT();
        issue(1, 1); CP_COMMIT();
        int cs = 0, ns_slot = 2;

        for (int t = 0; t < 16; t++) {
            CP_WAIT1();
            __syncthreads();
            const uint32_t abase = sb + cs * STP;
            const uint32_t bbase = abase + 16384;
            if (t + 2 < 16) issue(ns_slot, t + 2);
            CP_COMMIT();

            #pragma unroll
            for (int s = 0; s < 4; s++) {
                uint32_t afr[2][4], bfr[4][2];
                #pragma unroll
                for (int mt = 0; mt < 2; mt++) {
                    const int row0 = wm * 32 + mt * 16 + lm_row;
                    ldsm_x4(afr[mt], abase + (uint32_t)(row0 * 128)
                                           + ((uint32_t)((2 * s + hi) ^ rm) << 4));
                }
                #pragma unroll
                for (int nb = 0; nb < 2; nb++) {
                    uint32_t r[4];
                    const int krow = 16 * s + lm_row;
                    ldsm_x4_t(r, bbase + (uint32_t)(krow * 80)
                                       + (uint32_t)((nb * 2 + hi) * 16));
                    bfr[2 * nb][0] = r[0]; bfr[2 * nb][1] = r[1];
                    bfr[2 * nb + 1][0] = r[2]; bfr[2 * nb + 1][1] = r[3];
                }
                #pragma unroll
                for (int mt = 0; mt < 2; mt++)
                    #pragma unroll
                    for (int nt = 0; nt < 4; nt++)
                        mma_f16(acc[mt][nt], afr[mt], bfr[nt]);
            }
            cs      = (cs == 2) ? 0 : cs + 1;
            ns_slot = (ns_slot == 2) ? 0 : ns_slot + 1;
        }

        #pragma unroll
        for (int mt = 0; mt < 2; mt++) {
            const int row = mblk + wm * 32 + mt * 16 + gid;
            #pragma unroll
            for (int nt = 0; nt < 4; nt++) {
                const int col = nt * 8 + 2 * tig;
                const float b0 = bc[col], b1 = bc[col + 1];
                float2 v0 = { acc[mt][nt][0] * OSCALE + b0, acc[mt][nt][1] * OSCALE + b1 };
                float2 v1 = { acc[mt][nt][2] * OSCALE + b0, acc[mt][nt][3] * OSCALE + b1 };
                *reinterpret_cast<float2*>(&out[OFF_PLOG + row * N_CLS + col])       = v0;
                *reinterpret_cast<float2*>(&out[OFF_PLOG + (row + 8) * N_CLS + col]) = v1;
            }
        }
        return;
    }

    const int cbk   = blockIdx.x - 32;
    const int cls   = cbk >> 2;
    const int chunk = cbk & 3;
    const int cnt   = g_cnt[cls];
    const int base  = chunk * 128;
    if (base >= cnt) return;
    const int ns = min(128, cnt - base);

    __shared__ int sidx[128];
    sidx[tid] = g_idx[cls][base + min(tid, ns - 1)];
    __syncthreads();

    float acc[2][12][4];
    #pragma unroll
    for (int mt = 0; mt < 2; mt++)
        #pragma unroll
        for (int nt = 0; nt < 12; nt++)
            #pragma unroll
            for (int i = 0; i < 4; i++) acc[mt][nt][i] = 0.f;

    const __half* Bsrc = g_cwh + (size_t)cls * 96 * D_PROJ;

    auto issue = [&](int slot, int t) {
        const uint32_t abase = sb + slot * STC;
        const uint32_t bbase = abase + 16384;
        #pragma unroll
        for (int j = 0; j < 8; j++) {
            const int id = tid + 128 * j;
            const int row = id >> 3, c = id & 7;
            const __half* g = g_sh + (size_t)sidx[row] * D_PROJ + t * 64 + c * 8;
            CP_ASYNC16(abase + row * 128 + ((c ^ (row & 7)) << 4), g);
        }
        #pragma unroll
        for (int j = 0; j < 6; j++) {
            const int id = tid + 128 * j;
            const int row = id >> 3, c = id & 7;
            const __half* g = Bsrc + (size_t)row * D_PROJ + t * 64 + c * 8;
            CP_ASYNC16(bbase + row * 128 + ((c ^ (row & 7)) << 4), g);
        }
    };

    issue(0, 0); CP_COMMIT();
    issue(1, 1); CP_COMMIT();
    int cs = 0, ns_slot = 2;

    for (int t = 0; t < 16; t++) {
        CP_WAIT1();
        __syncthreads();
        const uint32_t abase = sb + cs * STC;
        const uint32_t bbase = abase + 16384;
        if (t + 2 < 16) issue(ns_slot, t + 2);
        CP_COMMIT();

        #pragma unroll
        for (int s = 0; s < 4; s++) {
            uint32_t afr[2][4], bfr[12][2];
            #pragma unroll
            for (int mt = 0; mt < 2; mt++) {
                const int row0 = wm * 32 + mt * 16 + lm_row;
                ldsm_x4(afr[mt], abase + (uint32_t)(row0 * 128)
                                       + ((uint32_t)((2 * s + hi) ^ rm) << 4));
            }
            #pragma unroll
            for (int nb = 0; nb < 6; nb++) {
                uint32_t r[4];
                const int row0 = nb * 16 + lm_row;
                ldsm_x4(r, bbase + (uint32_t)(row0 * 128)
                                 + ((uint32_t)((2 * s + hi) ^ rm) << 4));
                bfr[2 * nb][0] = r[0]; bfr[2 * nb][1] = r[2];
                bfr[2 * nb + 1][0] = r[1]; bfr[2 * nb + 1][1] = r[3];
            }
            #pragma unroll
            for (int mt = 0; mt < 2; mt++)
                #pragma unroll
                for (int nt = 0; nt < 12; nt++)
                    mma_f16(acc[mt][nt], afr[mt], bfr[nt]);
        }
        cs      = (cs == 2) ? 0 : cs + 1;
        ns_slot = (ns_slot == 2) ? 0 : ns_slot + 1;
    }

    #pragma unroll
    for (int mt = 0; mt < 2; mt++) {
        const int s0 = wm * 32 + mt * 16 + gid;
        #pragma unroll
        for (int half = 0; half < 2; half++) {
            const int s = s0 + half * 8;
            if (s < ns) {
                const int g = sidx[s];
                #pragma unroll
                for (int nt = 0; nt < 12; nt++) {
                    const int o = nt * 8 + 2 * tig;
                    const float a0 = acc[mt][nt][2 * half + 0] * OSCALE;
                    const float a1 = acc[mt][nt][2 * half + 1] * OSCALE;
                    if (o < NC0) {
                        float2 v = { a0 + cb0[cls * NC0 + o], a1 + cb0[cls * NC0 + o + 1] };
                        *reinterpret_cast<float2*>(&out[OFF_C0 + g * NC0 + o]) = v;
                    } else {
                        const int o1 = o - NC0;
                        float2 v = { a0 + cb1[cls * NC1 + o1], a1 + cb1[cls * NC1 + o1 + 1] };
                        *reinterpret_cast<float2*>(&out[OFF_C1 + g * NC1 + o1]) = v;
                    }
                }
            }
        }
    }
}

// ===========================================================================
// Launch: 3 kernels total
// ===========================================================================
extern "C" void kernel_launch(void* const* d_in, const int* in_sizes, int n_in,
                              void* d_out, int out_size)
{
    const float* x   = (const float*)d_in[0];
    const int*   y   = (const int*)  d_in[1];
    const float* Wp  = (const float*)d_in[2];
    const float* bp  = (const float*)d_in[3];
    const float* Ws  = (const float*)d_in[4];
    const float* bs  = (const float*)d_in[5];
    const float* Wc  = (const float*)d_in[6];
    const float* bc  = (const float*)d_in[7];
    const float* cw0 = (const float*)d_in[8];
    const float* cb0 = (const float*)d_in[9];
    const float* cw1 = (const float*)d_in[10];
    const float* cb1 = (const float*)d_in[11];
    float* out = (float*)d_out;

    static bool attr_set = false;
    if (!attr_set) {
        cudaFuncSetAttribute(hgemm_fused, cudaFuncAttributeMaxDynamicSharedMemorySize, SMEM_GEMM);
        cudaFuncSetAttribute(tail_kernel, cudaFuncAttributeMaxDynamicSharedMemorySize, SMEM_TAIL);
        attr_set = true;
    }

    // 1) fp16 pre-conversion + g_cnt zeroing
    convert_kernel<<<(NCONV2 + 255) / 256, 256>>>(x, Wp, Ws, cw0, cw1, Wc);

    // 2) fused dual-output GEMM (+ bucket row by==32)
    dim3 grid(D_PROJ / 128, B_ / 128 + 1);   // (8, 33)
    hgemm_fused<<<grid, 256, SMEM_GEMM>>>(y, bp, bs, out);

    // 3) tensor-core tail: parent logits + child expert logits
    tail_kernel<<<32 + N_CLS * 4, 128, SMEM_TAIL>>>(bc, cb0, cb1, out);
}

// round 12
// speedup vs baseline: 1.1603x; 1.1603x over previous
#include <cuda_runtime.h>
#include <cuda_fp16.h>
#include <cstdint>

// Problem constants
#define B_     4096
#define D_INN  4096
#define D_PROJ 1024
#define N_CLS  32
#define NC0    32
#define NC1    64

// Output layout: (parent_logits, child0, child1, parent_proj, child_proj) flattened fp32
#define OFF_PLOG 0
#define OFF_C0   (B_ * N_CLS)                 // 131072
#define OFF_C1   (OFF_C0 + B_ * NC0)          // 262144
#define OFF_P    (OFF_C1 + B_ * NC1)          // 524288
#define OFF_S    (OFF_P + B_ * D_PROJ)        // 4718592

#define WSCALE 4096.0f
#define OSCALE (1.0f / 4096.0f)

// fp16 scratch + bucket/dependency state (static device globals)
__device__ __align__(16) __half g_xh[B_ * D_INN];            // 32 MB
__device__ __align__(16) __half g_wph[D_INN * D_PROJ];       // 8 MB (x WSCALE)
__device__ __align__(16) __half g_wsh[D_INN * D_PROJ];       // 8 MB (x WSCALE)
__device__ __align__(16) __half g_ph[B_ * D_PROJ];           // 8 MB, P fp16
__device__ __align__(16) __half g_sh[B_ * D_PROJ];           // 8 MB, S fp16
__device__ __align__(16) __half g_cwh[N_CLS * 96 * D_PROJ];  // 6 MB, merged cw (x WSCALE)
__device__ __align__(16) __half g_wch[D_PROJ * N_CLS];       // 64 KB, Wc (x WSCALE)
__device__ int g_cnt[N_CLS];
__device__ int g_idx[N_CLS][B_];
// dependency counters (zeroed each call by convert_kernel block 0)
__device__ int g_pdone[32];   // per m-row-block of P
__device__ int g_sdone;      // S CTAs finished (target 256)
__device__ int g_bdone;      // bucket blocks finished (target 32)
__device__ int g_wcdone;     // Wc-convert blocks finished (target 32)
__device__ int g_cwdone[N_CLS]; // per-class cw-convert quarters (target 4)

// ===========================================================================
// helpers
// ===========================================================================
__device__ __forceinline__ uint32_t smem_u32(const void* p) {
    uint32_t a;
    asm("{ .reg .u64 t; cvta.to.shared.u64 t, %1; cvt.u32.u64 %0, t; }" : "=r"(a) : "l"(p));
    return a;
}

__device__ __forceinline__ uint32_t f2h2(float hi, float lo) {
    uint32_t r;
    asm("cvt.rn.f16x2.f32 %0, %1, %2;" : "=r"(r) : "f"(hi), "f"(lo));
    return r;
}

__device__ __forceinline__ void ldsm_x4(uint32_t* r, uint32_t addr) {
    asm volatile("ldmatrix.sync.aligned.m8n8.x4.shared.b16 {%0,%1,%2,%3}, [%4];"
                 : "=r"(r[0]), "=r"(r[1]), "=r"(r[2]), "=r"(r[3]) : "r"(addr));
}
__device__ __forceinline__ void ldsm_x4_t(uint32_t* r, uint32_t addr) {
    asm volatile("ldmatrix.sync.aligned.m8n8.x4.trans.shared.b16 {%0,%1,%2,%3}, [%4];"
                 : "=r"(r[0]), "=r"(r[1]), "=r"(r[2]), "=r"(r[3]) : "r"(addr));
}

__device__ __forceinline__ void mma_f16(float* d, const uint32_t* a, const uint32_t* b) {
    asm volatile(
        "mma.sync.aligned.m16n8k16.row.col.f32.f16.f16.f32 "
        "{%0,%1,%2,%3}, {%4,%5,%6,%7}, {%8,%9}, {%0,%1,%2,%3};"
        : "+f"(d[0]), "+f"(d[1]), "+f"(d[2]), "+f"(d[3])
        : "r"(a[0]), "r"(a[1]), "r"(a[2]), "r"(a[3]), "r"(b[0]), "r"(b[1]));
}

#define CP_ASYNC16(saddr, gaddr) \
    asm volatile("cp.async.cg.shared.global [%0], [%1], 16;" :: "r"(saddr), "l"(gaddr))
#define CP_COMMIT() asm volatile("cp.async.commit_group;" ::: "memory")
#define CP_WAIT1()  asm volatile("cp.async.wait_group 1;"  ::: "memory")

// Completion signal: all threads' stores -> fence -> sync -> one atomic.
__device__ __forceinline__ void signal_done(int* ctr) {
    __threadfence();
    __syncthreads();
    if (threadIdx.x == 0) atomicAdd(ctr, 1);
}
// Spin until *ctr >= target (device-scope atomic read), then fence.
__device__ __forceinline__ void spin_until(int* ctr, int target) {
    if (threadIdx.x == 0)
        while (atomicAdd(ctr, 0) < target) __nanosleep(128);
    __syncthreads();
    __threadfence();
}

// ===========================================================================
// K0: fp32 -> fp16 pre-conversion of x, Wp*WS, Ws*WS + counter zeroing.
// (cw/Wc conversion moved into the mega kernel's tail blocks.)
// ===========================================================================
#define NXF4  (B_ * D_INN / 4)           // 4194304
#define NWF4  (D_INN * D_PROJ / 4)       // 1048576
#define NCONVA (NXF4 + 2 * NWF4)         // 6291456
#define NCONVA2 (NCONVA / 2)

__global__ __launch_bounds__(256)
void convert_kernel(const float* __restrict__ x,
                    const float* __restrict__ Wp, const float* __restrict__ Ws)
{
    if (blockIdx.x == 0) {
        const int t = threadIdx.x;
        if (t < N_CLS) { g_cnt[t] = 0; g_pdone[t] = 0; g_cwdone[t] = 0; }
        else if (t == 32) g_sdone = 0;
        else if (t == 33) g_bdone = 0;
        else if (t == 34) g_wcdone = 0;
    }

    const int p = blockIdx.x * blockDim.x + threadIdx.x;
    if (p >= NCONVA2) return;
    const int i = p * 2;

    if (i < NXF4) {
        float4 v0 = *reinterpret_cast<const float4*>(x + (size_t)i * 4);
        float4 v1 = *reinterpret_cast<const float4*>(x + (size_t)i * 4 + 4);
        uint4 h = { f2h2(v0.y, v0.x), f2h2(v0.w, v0.z), f2h2(v1.y, v1.x), f2h2(v1.w, v1.z) };
        *reinterpret_cast<uint4*>(&g_xh[(size_t)i * 4]) = h;
    } else if (i < NXF4 + NWF4) {
        const int j = i - NXF4;
        float4 v0 = *reinterpret_cast<const float4*>(Wp + (size_t)j * 4);
        float4 v1 = *reinterpret_cast<const float4*>(Wp + (size_t)j * 4 + 4);
        uint4 h = { f2h2(v0.y * WSCALE, v0.x * WSCALE), f2h2(v0.w * WSCALE, v0.z * WSCALE),
                    f2h2(v1.y * WSCALE, v1.x * WSCALE), f2h2(v1.w * WSCALE, v1.z * WSCALE) };
        *reinterpret_cast<uint4*>(&g_wph[(size_t)j * 4]) = h;
    } else {
        const int j = i - NXF4 - NWF4;
        float4 v0 = *reinterpret_cast<const float4*>(Ws + (size_t)j * 4);
        float4 v1 = *reinterpret_cast<const float4*>(Ws + (size_t)j * 4 + 4);
        uint4 h = { f2h2(v0.y * WSCALE, v0.x * WSCALE), f2h2(v0.w * WSCALE, v0.z * WSCALE),
                    f2h2(v1.y * WSCALE, v1.x * WSCALE), f2h2(v1.w * WSCALE, v1.z * WSCALE) };
        *reinterpret_cast<uint4*>(&g_wsh[(size_t)j * 4]) = h;
    }
}

// ===========================================================================
// Mega kernel.
// z=0: S = x@Ws GEMM (R10 core, 4 warps, 64x64 warp tiles)  -> g_sdone
// z=1: P = x@Wp GEMM                                         -> g_pdone[by]
// z=2: flat<32 bucket; 32..63 plog (convert Wc slice, wait, TC plog);
//      64..191 child (convert cw quarter, wait, TC child); rest exit.
// S runs in wave 1 (enumeration order), so child blocks overlap P's wave 2.
// ===========================================================================
#define STAGES 3
#define BKH    64
#define A_ST_BYTES (128 * 128)               // 16384
#define B_ST_BYTES (64 * 256)                // 16384
#define ST_BYTES   (A_ST_BYTES + B_ST_BYTES) // 32768
#define SMEM_MEGA  (STAGES * ST_BYTES)       // 98304

#define STP (16384 + 64 * 80)    // 21504  (plog stage)
#define STC (16384 + 96 * 128)   // 28672  (child stage)

__global__ __launch_bounds__(128, 2)
void mega_kernel(const int* __restrict__ y,
                 const float* __restrict__ bp, const float* __restrict__ bs,
                 const float* __restrict__ Wc, const float* __restrict__ bc,
                 const float* __restrict__ cw0, const float* __restrict__ cb0,
                 const float* __restrict__ cw1, const float* __restrict__ cb1,
                 float* __restrict__ out)
{
    extern __shared__ char sm[];
    const uint32_t sb = smem_u32(sm);

    const int tid  = threadIdx.x;
    const int warp = tid >> 5;
    const int lane = tid & 31;
    const int lm_row = (lane & 7) + ((lane >> 3) & 1) * 8;  // 0..15
    const int hi     = lane >> 4;                           // 0..1
    const int rm     = lm_row & 7;
    const int gid    = lane >> 2;
    const int tig    = lane & 3;

    const int z = blockIdx.z;

    if (z < 2) {
        // =================== GEMM planes (R10 core) ===================
        const __half* __restrict__ Wh  = (z == 0) ? g_wsh : g_wph;
        const float*  __restrict__ bias = (z == 0) ? bs : bp;
        float* __restrict__ C  = out + ((z == 0) ? OFF_S : OFF_P);
        __half* __restrict__ Ch = (z == 0) ? g_sh : g_ph;

        const int wm   = warp >> 1;   // 0..1
        const int wn   = warp & 1;    // 0..1
        const int mblk = blockIdx.y * 128;
        const int nblk = blockIdx.x * 128;

        float acc[4][8][4];
        #pragma unroll
        for (int mt = 0; mt < 4; mt++)
            #pragma unroll
            for (int nt = 0; nt < 8; nt++)
                #pragma unroll
                for (int i = 0; i < 4; i++) acc[mt][nt][i] = 0.f;

        auto issue = [&](uint32_t abase, int t) {
            const uint32_t bbase = abase + A_ST_BYTES;
            #pragma unroll
            for (int j = 0; j < 8; j++) {
                const int id  = tid + 128 * j;
                const int row = id >> 3, c = id & 7;
                const __half* g = g_xh + (size_t)(mblk + row) * D_INN + t * BKH + c * 8;
                CP_ASYNC16(abase + row * 128 + ((c ^ (row & 7)) << 4), g);
            }
            #pragma unroll
            for (int j = 0; j < 8; j++) {
                const int id = tid + 128 * j;
                const int k  = id >> 4, c = id & 15;
                const __half* g = Wh + (size_t)(t * BKH + k) * D_PROJ + nblk + c * 8;
                CP_ASYNC16(bbase + k * 256 + ((c ^ (k & 7)) << 4), g);
            }
        };

        auto load_frags = [&](uint32_t abase, int s, uint32_t (&af)[4][4], uint32_t (&bf)[8][2]) {
            const uint32_t bbase = abase + A_ST_BYTES;
            #pragma unroll
            for (int mt = 0; mt < 4; mt++) {
                const int row0 = wm * 64 + mt * 16 + lm_row;
                ldsm_x4(af[mt], abase + (uint32_t)(row0 * 128)
                                      + ((uint32_t)((2 * s + hi) ^ rm) << 4));
            }
            #pragma unroll
            for (int nb = 0; nb < 4; nb++) {
                uint32_t r[4];
                const int krow = 16 * s + lm_row;
                ldsm_x4_t(r, bbase + (uint32_t)(krow * 256)
                                   + ((uint32_t)((wn * 8 + nb * 2 + hi) ^ rm) << 4));
                bf[2 * nb][0] = r[0]; bf[2 * nb][1] = r[1];
                bf[2 * nb + 1][0] = r[2]; bf[2 * nb + 1][1] = r[3];
            }
        };

        uint32_t afr[2][4][4], bfr[2][8][2];

        auto body = [&](int t, uint32_t cbase, uint32_t pbase) {
            CP_WAIT1();
            __syncthreads();

            load_frags(cbase, 0, afr[0], bfr[0]);

            if (t + 2 < 64)
                issue(pbase, t + 2);
            CP_COMMIT();

            #pragma unroll
            for (int s = 0; s < 4; s++) {
                if (s < 3)
                    load_frags(cbase, s + 1, afr[(s + 1) & 1], bfr[(s + 1) & 1]);
                const int cur = s & 1;
                #pragma unroll
                for (int mt = 0; mt < 4; mt++)
                    #pragma unroll
                    for (int nt = 0; nt < 8; nt++)
                        mma_f16(acc[mt][nt], afr[cur][mt], bfr[cur][nt]);
            }
        };

        const uint32_t s0 = sb, s1 = sb + ST_BYTES, s2 = sb + 2 * ST_BYTES;

        issue(s0, 0); CP_COMMIT();
        issue(s1, 1); CP_COMMIT();

        for (int t = 0; t < 63; t += 3) {
            body(t,     s0, s2);
            body(t + 1, s1, s0);
            body(t + 2, s2, s1);
        }
        body(63, s0, s2);

        #pragma unroll
        for (int mt = 0; mt < 4; mt++) {
            const int row = mblk + wm * 64 + mt * 16 + gid;
            #pragma unroll
            for (int nt = 0; nt < 8; nt++) {
                const int col = nblk + wn * 64 + nt * 8 + 2 * tig;
                const float b0 = bias[col], b1 = bias[col + 1];
                float2 v0 = { acc[mt][nt][0] * OSCALE + b0, acc[mt][nt][1] * OSCALE + b1 };
                float2 v1 = { acc[mt][nt][2] * OSCALE + b0, acc[mt][nt][3] * OSCALE + b1 };
                *reinterpret_cast<float2*>(&C[(size_t)row * D_PROJ + col])       = v0;
                *reinterpret_cast<float2*>(&C[(size_t)(row + 8) * D_PROJ + col]) = v1;
                *reinterpret_cast<uint32_t*>(&Ch[(size_t)row * D_PROJ + col])       = f2h2(v0.y, v0.x);
                *reinterpret_cast<uint32_t*>(&Ch[(size_t)(row + 8) * D_PROJ + col]) = f2h2(v1.y, v1.x);
            }
        }

        signal_done((z == 0) ? &g_sdone : &g_pdone[blockIdx.y]);
        return;
    }

    // ======================= z == 2 : tail plane =======================
    const int flat = blockIdx.x + 8 * blockIdx.y;   // 0..255

    if (flat < 32) {
        // ---- bucket: 32 blocks x 128 threads = 4096 samples ----
        const int b = flat * 128 + tid;
        const int c = y[b];
        const int p = atomicAdd(&g_cnt[c], 1);
        g_idx[c][p] = b;
        signal_done(&g_bdone);
        return;
    }

    if (flat < 64) {
        // ---- parent logits block ----
        const int by   = flat - 32;
        const int mblk = by * 128;

        // convert this block's Wc slice (128 pairs of float4)
        {
            const int q = by * 128 + tid;          // 0..4095
            const size_t f4 = (size_t)q * 2;
            float4 v0 = *reinterpret_cast<const float4*>(Wc + f4 * 4);
            float4 v1 = *reinterpret_cast<const float4*>(Wc + f4 * 4 + 4);
            uint4 h = { f2h2(v0.y * WSCALE, v0.x * WSCALE), f2h2(v0.w * WSCALE, v0.z * WSCALE),
                        f2h2(v1.y * WSCALE, v1.x * WSCALE), f2h2(v1.w * WSCALE, v1.z * WSCALE) };
            *reinterpret_cast<uint4*>(&g_wch[f4 * 4]) = h;
        }
        signal_done(&g_wcdone);
        spin_until(&g_wcdone, 32);
        spin_until(&g_pdone[by], 8);

        float acc[2][4][4];
        #pragma unroll
        for (int mt = 0; mt < 2; mt++)
            #pragma unroll
            for (int nt = 0; nt < 4; nt++)
                #pragma unroll
                for (int i = 0; i < 4; i++) acc[mt][nt][i] = 0.f;

        auto issue = [&](int slot, int t) {
            const uint32_t abase = sb + slot * STP;
            const uint32_t bbase = abase + 16384;
            #pragma unroll
            for (int j = 0; j < 8; j++) {
                const int id = tid + 128 * j;
                const int row = id >> 3, c = id & 7;
                const __half* g = g_ph + (size_t)(mblk + row) * D_PROJ + t * 64 + c * 8;
                CP_ASYNC16(abase + row * 128 + ((c ^ (row & 7)) << 4), g);
            }
            #pragma unroll
            for (int j = 0; j < 2; j++) {
                const int id = tid + 128 * j;
                const int row = id >> 2, c = id & 3;
                const __half* g = g_wch + (size_t)(t * 64 + row) * N_CLS + c * 8;
                CP_ASYNC16(bbase + row * 80 + c * 16, g);
            }
        };

        issue(0, 0); CP_COMMIT();
        issue(1, 1); CP_COMMIT();
        int cs = 0, ns_slot = 2;

        for (int t = 0; t < 16; t++) {
            CP_WAIT1();
            __syncthreads();
            const uint32_t abase = sb + cs * STP;
            const uint32_t bbase = abase + 16384;
            if (t + 2 < 16) issue(ns_slot, t + 2);
            CP_COMMIT();

            #pragma unroll
            for (int s = 0; s < 4; s++) {
                uint32_t afr[2][4], bfr[4][2];
                #pragma unroll
                for (int mt = 0; mt < 2; mt++) {
                    const int row0 = warp * 32 + mt * 16 + lm_row;
                    ldsm_x4(afr[mt], abase + (uint32_t)(row0 * 128)
                                           + ((uint32_t)((2 * s + hi) ^ rm) << 4));
                }
                #pragma unroll
                for (int nb = 0; nb < 2; nb++) {
                    uint32_t r[4];
                    const int krow = 16 * s + lm_row;
                    ldsm_x4_t(r, bbase + (uint32_t)(krow * 80)
                                       + (uint32_t)((nb * 2 + hi) * 16));
                    bfr[2 * nb][0] = r[0]; bfr[2 * nb][1] = r[1];
                    bfr[2 * nb + 1][0] = r[2]; bfr[2 * nb + 1][1] = r[3];
                }
                #pragma unroll
                for (int mt = 0; mt < 2; mt++)
                    #pragma unroll
                    for (int nt = 0; nt < 4; nt++)
                        mma_f16(acc[mt][nt], afr[mt], bfr[nt]);
            }
            cs      = (cs == 2) ? 0 : cs + 1;
            ns_slot = (ns_slot == 2) ? 0 : ns_slot + 1;
        }

        #pragma unroll
        for (int mt = 0; mt < 2; mt++) {
            const int row = mblk + warp * 32 + mt * 16 + gid;
            #pragma unroll
            for (int nt = 0; nt < 4; nt++) {
                const int col = nt * 8 + 2 * tig;
                const float b0 = bc[col], b1 = bc[col + 1];
                float2 v0 = { acc[mt][nt][0] * OSCALE + b0, acc[mt][nt][1] * OSCALE + b1 };
                float2 v1 = { acc[mt][nt][2] * OSCALE + b0, acc[mt][nt][3] * OSCALE + b1 };
                *reinterpret_cast<float2*>(&out[OFF_PLOG + row * N_CLS + col])       = v0;
                *reinterpret_cast<float2*>(&out[OFF_PLOG + (row + 8) * N_CLS + col]) = v1;
            }
        }
        return;
    }

    if (flat >= 192) return;

    // ---- child expert block ----
    const int cbk   = flat - 64;
    const int cls   = cbk >> 2;
    const int chunk = cbk & 3;

    // convert this block's quarter of the class cw slab (6144 float4 = 3072 pairs)
    {
        const float* w0 = cw0 + (size_t)cls * NC0 * D_PROJ;
        const float* w1 = cw1 + (size_t)cls * NC1 * D_PROJ;
        #pragma unroll 4
        for (int j = 0; j < 24; j++) {
            const int pr = tid + j * 128;               // 0..3071
            const int lf = chunk * 6144 + pr * 2;       // f4 index in slab (even)
            const int o  = lf >> 8;                      // 0..95
            const int k  = (lf & 255) * 4;               // float offset in row
            const float* src = (o < NC0) ? (w0 + (size_t)o * D_PROJ + k)
                                         : (w1 + (size_t)(o - NC0) * D_PROJ + k);
            float4 v0 = *reinterpret_cast<const float4*>(src);
            float4 v1 = *reinterpret_cast<const float4*>(src + 4);
            uint4 h = { f2h2(v0.y * WSCALE, v0.x * WSCALE), f2h2(v0.w * WSCALE, v0.z * WSCALE),
                        f2h2(v1.y * WSCALE, v1.x * WSCALE), f2h2(v1.w * WSCALE, v1.z * WSCALE) };
            *reinterpret_cast<uint4*>(&g_cwh[(size_t)cls * 96 * D_PROJ + (size_t)lf * 4]) = h;
        }
    }
    signal_done(&g_cwdone[cls]);

    spin_until(&g_bdone, 32);
    const int cnt  = __ldcg(&g_cnt[cls]);
    const int base = chunk * 128;
    if (base >= cnt) return;
    const int ns = min(128, cnt - base);

    spin_until(&g_cwdone[cls], 4);
    spin_until(&g_sdone, 256);

    __shared__ int sidx[128];
    sidx[tid] = __ldcg(&g_idx[cls][base + min(tid, ns - 1)]);
    __syncthreads();

    float acc[2][12][4];
    #pragma unroll
    for (int mt = 0; mt < 2; mt++)
        #pragma unroll
        for (int nt = 0; nt < 12; nt++)
            #pragma unroll
            for (int i = 0; i < 4; i++) acc[mt][nt][i] = 0.f;

    const __half* Bsrc = g_cwh + (size_t)cls * 96 * D_PROJ;

    auto issue = [&](int slot, int t) {
        const uint32_t abase = sb + slot * STC;
        const uint32_t bbase = abase + 16384;
        #pragma unroll
        for (int j = 0; j < 8; j++) {
            const int id = tid + 128 * j;
            const int row = id >> 3, c = id & 7;
            const __half* g = g_sh + (size_t)sidx[row] * D_PROJ + t * 64 + c * 8;
            CP_ASYNC16(abase + row * 128 + ((c ^ (row & 7)) << 4), g);
        }
        #pragma unroll
        for (int j = 0; j < 6; j++) {
            const int id = tid + 128 * j;
            const int row = id >> 3, c = id & 7;
            const __half* g = Bsrc + (size_t)row * D_PROJ + t * 64 + c * 8;
            CP_ASYNC16(bbase + row * 128 + ((c ^ (row & 7)) << 4), g);
        }
    };

    issue(0, 0); CP_COMMIT();
    issue(1, 1); CP_COMMIT();
    int cs = 0, ns_slot = 2;

    for (int t = 0; t < 16; t++) {
        CP_WAIT1();
        __syncthreads();
        const uint32_t abase = sb + cs * STC;
        const uint32_t bbase = abase + 16384;
        if (t + 2 < 16) issue(ns_slot, t + 2);
        CP_COMMIT();

        #pragma unroll
        for (int s = 0; s < 4; s++) {
            uint32_t afr[2][4], bfr[12][2];
            #pragma unroll
            for (int mt = 0; mt < 2; mt++) {
                const int row0 = warp * 32 + mt * 16 + lm_row;
                ldsm_x4(afr[mt], abase + (uint32_t)(row0 * 128)
                                       + ((uint32_t)((2 * s + hi) ^ rm) << 4));
            }
            #pragma unroll
            for (int nb = 0; nb < 6; nb++) {
                uint32_t r[4];
                const int row0 = nb * 16 + lm_row;
                ldsm_x4(r, bbase + (uint32_t)(row0 * 128)
                                 + ((uint32_t)((2 * s + hi) ^ rm) << 4));
                bfr[2 * nb][0] = r[0]; bfr[2 * nb][1] = r[2];
                bfr[2 * nb + 1][0] = r[1]; bfr[2 * nb + 1][1] = r[3];
            }
            #pragma unroll
            for (int mt = 0; mt < 2; mt++)
                #pragma unroll
                for (int nt = 0; nt < 12; nt++)
                    mma_f16(acc[mt][nt], afr[mt], bfr[nt]);
        }
        cs      = (cs == 2) ? 0 : cs + 1;
        ns_slot = (ns_slot == 2) ? 0 : ns_slot + 1;
    }

    #pragma unroll
    for (int mt = 0; mt < 2; mt++) {
        const int s0 = warp * 32 + mt * 16 + gid;
        #pragma unroll
        for (int half = 0; half < 2; half++) {
            const int s = s0 + half * 8;
            if (s < ns) {
                const int g = sidx[s];
                #pragma unroll
                for (int nt = 0; nt < 12; nt++) {
                    const int o = nt * 8 + 2 * tig;
                    const float a0 = acc[mt][nt][2 * half + 0] * OSCALE;
                    const float a1 = acc[mt][nt][2 * half + 1] * OSCALE;
                    if (o < NC0) {
                        float2 v = { a0 + cb0[cls * NC0 + o], a1 + cb0[cls * NC0 + o + 1] };
                        *reinterpret_cast<float2*>(&out[OFF_C0 + g * NC0 + o]) = v;
                    } else {
                        const int o1 = o - NC0;
                        float2 v = { a0 + cb1[cls * NC1 + o1], a1 + cb1[cls * NC1 + o1 + 1] };
                        *reinterpret_cast<float2*>(&out[OFF_C1 + g * NC1 + o1]) = v;
                    }
                }
            }
        }
    }
}

// ===========================================================================
// Launch: 2 kernels total
// ===========================================================================
extern "C" void kernel_launch(void* const* d_in, const int* in_sizes, int n_in,
                              void* d_out, int out_size)
{
    const float* x   = (const float*)d_in[0];
    const int*   y   = (const int*)  d_in[1];
    const float* Wp  = (const float*)d_in[2];
    const float* bp  = (const float*)d_in[3];
    const float* Ws  = (const float*)d_in[4];
    const float* bs  = (const float*)d_in[5];
    const float* Wc  = (const float*)d_in[6];
    const float* bc  = (const float*)d_in[7];
    const float* cw0 = (const float*)d_in[8];
    const float* cb0 = (const float*)d_in[9];
    const float* cw1 = (const float*)d_in[10];
    const float* cb1 = (const float*)d_in[11];
    float* out = (float*)d_out;

    static bool attr_set = false;
    if (!attr_set) {
        cudaFuncSetAttribute(mega_kernel, cudaFuncAttributeMaxDynamicSharedMemorySize, SMEM_MEGA);
        attr_set = true;
    }

    // 1) fp16 pre-conversion of x/Wp/Ws + counter zeroing
    convert_kernel<<<(NCONVA2 + 255) / 256, 256>>>(x, Wp, Ws);

    // 2) mega kernel: S-GEMM (z=0), P-GEMM (z=1), bucket+plog+child (z=2)
    dim3 grid(D_PROJ / 128, B_ / 128, 3);   // (8, 32, 3)
    mega_kernel<<<grid, 128, SMEM_MEGA>>>(y, bp, bs, Wc, bc, cw0, cb0, cw1, cb1, out);
}